// round 1
// baseline (speedup 1.0000x reference)
#include <cuda_runtime.h>
#include <math.h>

// ---------------- problem constants ----------------
#define N_SW   131
#define NC2    (N_SW*N_SW)        // 17161
#define NLC    33                 // distinct |L-32| classes 0..32
#define NM     16                 // only m<16 are nonzero
#define BATCH  128
#define NV1    49                 // injection switches [0,49)
#define ROWS   (BATCH*NLC*NM)     // 67584 independent 131-dim complex systems

// ---------------- step-kernel tiling ----------------
#define TPB    512
#define WARPS  16
#define RPW    4                  // rows per warp
#define RPB    (WARPS*RPW)        // 64 rows per block
#define NBLK   (ROWS/RPB)         // 1056 (exact)
#define NSLOT  5                  // ceil(131/32) t-columns per lane

// dynamic smem layout
#define C_BYTES    (NC2*8)                    // 137288: C[s][t] as float2
#define OUT_OFF    C_BYTES
#define OUT_BYTES  (WARPS*RPW*N_SW*8)         // 67072: per-warp out rows
#define GAIN_OFF   (OUT_OFF+OUT_BYTES)        // 204360
#define SMEM_BYTES (GAIN_OFF + 544)           // 204904

// ---------------- persistent device scratch (no allocs allowed) ----------------
__device__ float2 g_field[(size_t)ROWS * N_SW];   // ~70.8 MB, rewritten fully every run
__device__ float2 g_C[NC2];                       // conn * e^{i*phase[t]}
__device__ float  g_gain[N_SW];                   // softplus(switch_gain)
__device__ float  g_pinj[BATCH * NM * NV1];       // 0.3/enc_max * p[b,s,m]
__device__ float  g_erow[10 * ROWS];              // per-row energy, final step
__device__ int    g_absmax_bits;

// ---------------- packed f32x2 helpers ----------------
__device__ __forceinline__ unsigned long long pack2(float x, float y) {
    unsigned long long r;
    asm("mov.b64 %0, {%1,%2};" : "=l"(r) : "f"(x), "f"(y));
    return r;
}
__device__ __forceinline__ void unpack2(unsigned long long v, float& x, float& y) {
    asm("mov.b64 {%0,%1}, %2;" : "=f"(x), "=f"(y) : "l"(v));
}
#define FMA2(acc, a, b) asm("fma.rn.f32x2 %0, %1, %2, %0;" : "+l"(acc) : "l"(a), "l"(b))

// ---------------- prep kernels ----------------
__global__ void k_init() {
    if (threadIdx.x == 0) g_absmax_bits = 0;
}

__global__ void k_absmax(const float* __restrict__ img, int n) {
    int i = blockIdx.x * blockDim.x + threadIdx.x;
    float v = (i < n) ? fabsf(img[i]) : 0.f;
    #pragma unroll
    for (int o = 16; o > 0; o >>= 1) v = fmaxf(v, __shfl_xor_sync(0xffffffffu, v, o));
    if ((threadIdx.x & 31) == 0) atomicMax(&g_absmax_bits, __float_as_int(v));
}

__global__ void k_prep(const float* __restrict__ cr, const float* __restrict__ ci,
                       const float* __restrict__ ph, const float* __restrict__ sg) {
    int i = blockIdx.x * blockDim.x + threadIdx.x;
    if (i < NC2) {
        int t = i % N_SW;
        float sp, cp;
        sincosf(ph[t], &sp, &cp);
        float a = cr[i], b = ci[i];
        g_C[i] = make_float2(a * cp - b * sp, a * sp + b * cp);  // conn * e^{i phase[t]}
    }
    if (i < N_SW) {
        float x = sg[i];                                          // softplus, stable
        g_gain[i] = fmaxf(x, 0.f) + log1pf(expf(-fabsf(x)));
    }
}

__global__ void k_pinj(const float* __restrict__ img) {
    int i = blockIdx.x * blockDim.x + threadIdx.x;
    if (i >= BATCH * NM * NV1) return;
    int b   = i / (NM * NV1);
    int rem = i - b * (NM * NV1);
    int m   = rem / NV1;
    int s   = rem - m * NV1;
    int pr = s / 7, pc = s - pr * 7;
    int ir = m >> 2, ic = m & 3;
    float am   = __int_as_float(g_absmax_bits);
    float coef = (am > 1e-8f) ? 0.3f / am : 0.3f;
    g_pinj[i] = coef * img[b * 784 + (pr * 4 + ir) * 28 + (pc * 4 + ic)];
}

// ---------------- main recurrence step ----------------
__global__ __launch_bounds__(TPB) void k_step(int step,
                                              const int* __restrict__ nsp,
                                              const int* __restrict__ injp) {
    extern __shared__ unsigned char smem[];
    float2* Csh     = (float2*)(smem);
    float2* out_sh  = (float2*)(smem + OUT_OFF);
    float*  gain_sh = (float*)(smem + GAIN_OFF);

    const int ns = *nsp;
    if (step >= ns) return;
    const int injs = *injp;

    for (int i = threadIdx.x; i < NC2; i += TPB) Csh[i] = g_C[i];
    for (int i = threadIdx.x; i < N_SW; i += TPB) gain_sh[i] = g_gain[i];
    __syncthreads();

    const int warp = threadIdx.x >> 5;
    const int lane = threadIdx.x & 31;
    const int rowBase = blockIdx.x * RPB + warp * RPW;
    float2* outw = out_sh + (size_t)warp * RPW * N_SW;

    unsigned long long acc[RPW][NSLOT];
    #pragma unroll
    for (int r = 0; r < RPW; r++)
        #pragma unroll
        for (int j = 0; j < NSLOT; j++) acc[r][j] = 0ull;

    if (step > 0) {
        // Phase A: recompute out_{t-1} = field * tanh(|f|*g)/(|f|+eps) from stored field
        #pragma unroll
        for (int r = 0; r < RPW; r++) {
            const float2* f = g_field + (size_t)(rowBase + r) * N_SW;
            #pragma unroll
            for (int j = 0; j < NSLOT; j++) {
                int t = lane + 32 * j;
                if (t < N_SW) {
                    float2 fv = f[t];
                    float mag = sqrtf(fv.x * fv.x + fv.y * fv.y + 1e-8f);
                    float sc  = tanhf(mag * gain_sh[t]) / (mag + 1e-8f);
                    outw[r * N_SW + t] = make_float2(fv.x * sc, fv.y * sc);
                }
            }
        }
        __syncwarp();

        // Phase B: g[t] = sum_s out[s] * C[s][t]  (complex), packed f32x2 FMAs
        const unsigned long long* C64 = (const unsigned long long*)Csh;
        const unsigned long long* O64 = (const unsigned long long*)outw;
        for (int s = 0; s < N_SW; s++) {
            unsigned long long b1[NSLOT], b2[NSLOT];
            #pragma unroll
            for (int j = 0; j < NSLOT; j++) {
                unsigned long long c = C64[s * N_SW + lane + 32 * j];  // j=4 tail: in-smem, unused
                float cr, ci;
                unpack2(c, cr, ci);
                b1[j] = c;
                b2[j] = pack2(-ci, cr);
            }
            #pragma unroll
            for (int r = 0; r < RPW; r++) {
                float orr, oii;
                unpack2(O64[r * N_SW + s], orr, oii);
                unsigned long long a1 = pack2(orr, orr);
                unsigned long long a2 = pack2(oii, oii);
                #pragma unroll
                for (int j = 0; j < NSLOT; j++) {
                    FMA2(acc[r][j], a1, b1[j]);   // (gr += or*Cr, gi += or*Ci)
                    FMA2(acc[r][j], a2, b2[j]);   // (gr -= oi*Ci, gi += oi*Cr)
                }
            }
        }
    }

    // Phase C: field = (field + inj)*0.85 + g*0.25 ; final step -> per-row energy
    const bool inject = (step < injs);
    const bool last   = (step == ns - 1);
    #pragma unroll
    for (int r = 0; r < RPW; r++) {
        int grow = rowBase + r;
        int b    = grow / (NLC * NM);
        int rem  = grow - b * (NLC * NM);
        int lc   = rem / NM;
        int m    = rem - lc * NM;
        float w    = 1.0f - (float)lc * 0.015625f;                  // 1 - d/64
        float mult = (lc == 0 || lc == NLC - 1) ? 1.0f : 2.0f;
        float2* f = g_field + (size_t)grow * N_SW;
        const float* pj = g_pinj + (b * NM + m) * NV1;
        #pragma unroll
        for (int j = 0; j < NSLOT; j++) {
            int t = lane + 32 * j;
            if (t >= N_SW) continue;
            float fr = 0.f, fi = 0.f;
            if (step > 0) { float2 fv = f[t]; fr = fv.x; fi = fv.y; }
            if (inject && t < NV1) fr += pj[t] * w;
            float gr, gi;
            unpack2(acc[r][j], gr, gi);
            fr = fr * 0.85f + gr * 0.25f;
            fi = fi * 0.85f + gi * 0.25f;
            f[t] = make_float2(fr, fi);
            if (last && t >= 121) {
                float mag = sqrtf(fr * fr + fi * fi + 1e-8f);
                float sc  = tanhf(mag * gain_sh[t]) / (mag + 1e-8f);
                float orr = fr * sc, oii = fi * sc;
                g_erow[(t - 121) * ROWS + grow] = mult * (orr * orr + oii * oii);
            }
        }
    }
}

// ---------------- readout ----------------
__global__ void k_final(const float* __restrict__ rw, const float* __restrict__ rb,
                        float* __restrict__ out) {
    __shared__ float feat[10];
    int b = blockIdx.x;
    int warp = threadIdx.x >> 5, lane = threadIdx.x & 31;
    if (warp < 10) {
        float s = 0.f;
        const float* e = g_erow + warp * ROWS + b * (NLC * NM);
        for (int k = lane; k < NLC * NM; k += 32) s += e[k];
        #pragma unroll
        for (int o = 16; o > 0; o >>= 1) s += __shfl_xor_sync(0xffffffffu, s, o);
        if (lane == 0) feat[warp] = log1pf(s + 1e-8f);
    }
    __syncthreads();
    if (threadIdx.x < 10) {
        int c = threadIdx.x;
        float acc = rb[c];
        #pragma unroll
        for (int o = 0; o < 10; o++) acc += feat[o] * rw[c * 10 + o];
        out[b * 10 + c] = acc;
    }
}

// ---------------- entry ----------------
extern "C" void kernel_launch(void* const* d_in, const int* in_sizes, int n_in,
                              void* d_out, int out_size) {
    const float* images = (const float*)d_in[0];
    const float* conn_r = (const float*)d_in[1];
    const float* conn_i = (const float*)d_in[2];
    const float* ph     = (const float*)d_in[3];
    const float* sg     = (const float*)d_in[4];
    const float* rw     = (const float*)d_in[5];
    const float* rb     = (const float*)d_in[6];
    const int*   nsp    = (const int*)d_in[7];
    const int*   injp   = (const int*)d_in[8];

    cudaFuncSetAttribute(k_step, cudaFuncAttributeMaxDynamicSharedMemorySize, SMEM_BYTES);

    k_init<<<1, 32>>>();
    const int n_img = BATCH * 28 * 28;
    k_absmax<<<(n_img + 511) / 512, 512>>>(images, n_img);
    k_prep<<<(NC2 + 255) / 256, 256>>>(conn_r, conn_i, ph, sg);
    k_pinj<<<(BATCH * NM * NV1 + 255) / 256, 256>>>(images);

    for (int t = 0; t < 10; t++)
        k_step<<<NBLK, TPB, SMEM_BYTES>>>(t, nsp, injp);

    k_final<<<BATCH, 320>>>(rw, rb, (float*)d_out);
}